// round 2
// baseline (speedup 1.0000x reference)
#include <cuda_runtime.h>
#include <cstddef>

// Problem dims
#define B_  2
#define S_  2048
#define D_  1024
#define H_  16
#define DH_ 64
#define M_  (B_ * S_)          // 4096 rows for the [B*S, D] matmuls
#define SP1 (S_ + 1)           // 2049, rel-shift divisor

// ---------------------------------------------------------------------------
// Scratch (device globals; no cudaMalloc allowed)
// ---------------------------------------------------------------------------
__device__ float g_qh[(size_t)M_ * D_];        // [B,S,H,DH] head-interleaved
__device__ float g_kh[(size_t)M_ * D_];
__device__ float g_vh[(size_t)M_ * D_];
__device__ float g_ph[(size_t)M_ * D_];
__device__ float g_scores[(size_t)B_ * H_ * S_ * S_];  // content (+shifted pos) -> probs
__device__ float g_attout[(size_t)M_ * D_];            // [B,S,D] attn output

// ---------------------------------------------------------------------------
// Kernel 1: C[m,n] = A[m,:] . W[n,:] + bias[n]   (x @ W^T + b)
// M=4096, N=1024, K=1024. 128x128x16 tile, 8x8 microtile, 256 threads.
// ---------------------------------------------------------------------------
__global__ __launch_bounds__(256) void gemm_xwt(
    const float* __restrict__ A, const float* __restrict__ W,
    const float* __restrict__ bias, float* __restrict__ C,
    int Mdim, int Ndim, int Kdim)
{
    constexpr int BM = 128, BN = 128, BK = 16, TM = 8, TN = 8;
    __shared__ float As[BK][BM];
    __shared__ float Bs[BK][BN];

    const int tid = threadIdx.x;
    const int tr = tid >> 4;          // 0..15
    const int tc = tid & 15;          // 0..15
    const int bm = blockIdx.y * BM;
    const int bn = blockIdx.x * BN;

    float acc[TM][TN];
#pragma unroll
    for (int i = 0; i < TM; i++)
#pragma unroll
        for (int j = 0; j < TN; j++) acc[i][j] = 0.f;

    for (int k0 = 0; k0 < Kdim; k0 += BK) {
        // A tile: 128x16 floats = 512 float4, 2 per thread
#pragma unroll
        for (int i = tid; i < BM * BK / 4; i += 256) {
            int r = i >> 2;
            int c4 = (i & 3) * 4;
            float4 v = *(const float4*)&A[(size_t)(bm + r) * Kdim + k0 + c4];
            As[c4 + 0][r] = v.x; As[c4 + 1][r] = v.y;
            As[c4 + 2][r] = v.z; As[c4 + 3][r] = v.w;
        }
        // W tile: 128x16
#pragma unroll
        for (int i = tid; i < BN * BK / 4; i += 256) {
            int r = i >> 2;
            int c4 = (i & 3) * 4;
            float4 v = *(const float4*)&W[(size_t)(bn + r) * Kdim + k0 + c4];
            Bs[c4 + 0][r] = v.x; Bs[c4 + 1][r] = v.y;
            Bs[c4 + 2][r] = v.z; Bs[c4 + 3][r] = v.w;
        }
        __syncthreads();
#pragma unroll
        for (int kk = 0; kk < BK; kk++) {
            float ra[TM], rb[TN];
#pragma unroll
            for (int i = 0; i < TM; i++) ra[i] = As[kk][tr * TM + i];
#pragma unroll
            for (int j = 0; j < TN; j++) rb[j] = Bs[kk][tc * TN + j];
#pragma unroll
            for (int i = 0; i < TM; i++)
#pragma unroll
                for (int j = 0; j < TN; j++) acc[i][j] += ra[i] * rb[j];
        }
        __syncthreads();
    }

#pragma unroll
    for (int i = 0; i < TM; i++) {
        int m = bm + tr * TM + i;
#pragma unroll
        for (int j = 0; j < TN; j++) {
            int n = bn + tc * TN + j;
            float bb = bias ? bias[n] : 0.f;
            C[(size_t)m * Ndim + n] = acc[i][j] + bb;
        }
    }
}

// ---------------------------------------------------------------------------
// Kernel 2: per (b,h) score GEMM over DH=64:
//   acc[i,jj] = sum_d (A[b,i,h,d] + hbias[h,d]) * Bm[b,jj,h,d]
// mode 0 (content): out[z, i, jj]  = acc
// mode 1 (pos):     rel-shift scatter-accumulate:
//     flat = i*(S+1) + jj + 1;  q = flat/S - 1;  k = flat mod S
//     if (q >= 0) out[z, q, k] += acc        (injective -> race-free)
// 128x128 tile, K=64 in 4 steps of 16.
// ---------------------------------------------------------------------------
__global__ __launch_bounds__(256) void gemm_scores(
    const float* __restrict__ A, const float* __restrict__ Bm,
    const float* __restrict__ hbias, float* __restrict__ out, int mode)
{
    constexpr int BM = 128, BN = 128, BK = 16, TM = 8, TN = 8;
    __shared__ float As[BK][BM];
    __shared__ float Bs[BK][BN];

    const int z = blockIdx.z;         // b*H + h
    const int b = z >> 4;
    const int h = z & 15;
    const int bm = blockIdx.y * BM;
    const int bn = blockIdx.x * BN;
    const int tid = threadIdx.x;
    const int tr = tid >> 4;
    const int tc = tid & 15;

    const size_t baseA = (size_t)b * S_ * D_ + (size_t)h * DH_;

    float acc[TM][TN];
#pragma unroll
    for (int i = 0; i < TM; i++)
#pragma unroll
        for (int j = 0; j < TN; j++) acc[i][j] = 0.f;

    for (int k0 = 0; k0 < DH_; k0 += BK) {
#pragma unroll
        for (int i = tid; i < BM * BK / 4; i += 256) {
            int r = i >> 2;
            int c4 = (i & 3) * 4;
            float4 v  = *(const float4*)&A[baseA + (size_t)(bm + r) * D_ + k0 + c4];
            float4 bb = *(const float4*)&hbias[h * DH_ + k0 + c4];
            As[c4 + 0][r] = v.x + bb.x; As[c4 + 1][r] = v.y + bb.y;
            As[c4 + 2][r] = v.z + bb.z; As[c4 + 3][r] = v.w + bb.w;
        }
#pragma unroll
        for (int i = tid; i < BN * BK / 4; i += 256) {
            int r = i >> 2;
            int c4 = (i & 3) * 4;
            float4 v = *(const float4*)&Bm[baseA + (size_t)(bn + r) * D_ + k0 + c4];
            Bs[c4 + 0][r] = v.x; Bs[c4 + 1][r] = v.y;
            Bs[c4 + 2][r] = v.z; Bs[c4 + 3][r] = v.w;
        }
        __syncthreads();
#pragma unroll
        for (int kk = 0; kk < BK; kk++) {
            float ra[TM], rb[TN];
#pragma unroll
            for (int i = 0; i < TM; i++) ra[i] = As[kk][tr * TM + i];
#pragma unroll
            for (int j = 0; j < TN; j++) rb[j] = Bs[kk][tc * TN + j];
#pragma unroll
            for (int i = 0; i < TM; i++)
#pragma unroll
                for (int j = 0; j < TN; j++) acc[i][j] += ra[i] * rb[j];
        }
        __syncthreads();
    }

    const size_t obase = (size_t)z * S_ * S_;
    if (mode == 0) {
#pragma unroll
        for (int i = 0; i < TM; i++) {
            int q = bm + tr * TM + i;
#pragma unroll
            for (int j = 0; j < TN; j++) {
                int k = bn + tc * TN + j;
                out[obase + (size_t)q * S_ + k] = acc[i][j];
            }
        }
    } else {
#pragma unroll
        for (int i = 0; i < TM; i++) {
            int iq = bm + tr * TM + i;       // raw pos row
#pragma unroll
            for (int j = 0; j < TN; j++) {
                int jj = bn + tc * TN + j;   // raw pos col
                int flat = iq * SP1 + jj + 1;
                int qo = (flat >> 11) - 1;   // flat / 2048 - 1
                int ko = flat & (S_ - 1);    // flat mod 2048
                if (qo >= 0)
                    out[obase + (size_t)qo * S_ + ko] += acc[i][j];
            }
        }
    }
}

// ---------------------------------------------------------------------------
// Kernel 3: scale + softmax in place (scores already = content + shifted pos).
// One block per (b,h,q) row. 256 threads, 8 elems/thread.
// ---------------------------------------------------------------------------
__global__ __launch_bounds__(256) void softmax_rows(float* __restrict__ scores)
{
    const int row = blockIdx.x;        // 0 .. B*H*S-1
    float* crow = scores + (size_t)row * S_;
    const int t0 = threadIdx.x;

    float vals[8];
    float mx = -3.4e38f;
#pragma unroll
    for (int t = 0; t < 8; t++) {
        float s = crow[t0 + t * 256] * 0.03125f;   // 1/sqrt(1024)
        vals[t] = s;
        mx = fmaxf(mx, s);
    }

    __shared__ float smax[8];
    __shared__ float ssum[8];
#pragma unroll
    for (int o = 16; o > 0; o >>= 1) mx = fmaxf(mx, __shfl_xor_sync(0xffffffffu, mx, o));
    if ((t0 & 31) == 0) smax[t0 >> 5] = mx;
    __syncthreads();
    float rmax = smax[0];
#pragma unroll
    for (int w = 1; w < 8; w++) rmax = fmaxf(rmax, smax[w]);

    float sum = 0.f;
#pragma unroll
    for (int t = 0; t < 8; t++) {
        vals[t] = __expf(vals[t] - rmax);
        sum += vals[t];
    }
#pragma unroll
    for (int o = 16; o > 0; o >>= 1) sum += __shfl_xor_sync(0xffffffffu, sum, o);
    if ((t0 & 31) == 0) ssum[t0 >> 5] = sum;
    __syncthreads();
    float tot = 0.f;
#pragma unroll
    for (int w = 0; w < 8; w++) tot += ssum[w];
    const float inv = 1.f / tot;

#pragma unroll
    for (int t = 0; t < 8; t++) crow[t0 + t * 256] = vals[t] * inv;
}

// ---------------------------------------------------------------------------
// Kernel 4: attn @ V per (b,h):
//   outh[b,q,h,d] = sum_k prob[(b*H+h),q,k] * vh[b,k,h,d]
// M=2048 (q), N=64 (d, full), K=2048. 128x64x32 tile, 8x4 microtile.
// ---------------------------------------------------------------------------
__global__ __launch_bounds__(256) void gemm_av(
    const float* __restrict__ prob, const float* __restrict__ vh,
    float* __restrict__ outh)
{
    constexpr int BM = 128, BN = 64, BK = 32, TM = 8, TN = 4;
    __shared__ float As[BK][BM];   // 16 KB
    __shared__ float Bs[BK][BN];   // 8 KB

    const int z = blockIdx.z;      // b*H + h
    const int b = z >> 4;
    const int h = z & 15;
    const int bm = blockIdx.y * BM;
    const int tid = threadIdx.x;
    const int tr = tid >> 4;
    const int tc = tid & 15;

    const size_t pbase = (size_t)z * S_ * S_;
    const size_t vbase = (size_t)b * S_ * D_ + (size_t)h * DH_;

    float acc[TM][TN];
#pragma unroll
    for (int i = 0; i < TM; i++)
#pragma unroll
        for (int j = 0; j < TN; j++) acc[i][j] = 0.f;

    for (int k0 = 0; k0 < S_; k0 += BK) {
        // prob tile: 128 x 32 = 1024 float4, 4/thread
#pragma unroll
        for (int i = tid; i < BM * BK / 4; i += 256) {
            int r = i >> 3;
            int c4 = (i & 7) * 4;
            float4 v = *(const float4*)&prob[pbase + (size_t)(bm + r) * S_ + k0 + c4];
            As[c4 + 0][r] = v.x; As[c4 + 1][r] = v.y;
            As[c4 + 2][r] = v.z; As[c4 + 3][r] = v.w;
        }
        // vh tile: 32 x 64 = 512 float4, 2/thread
#pragma unroll
        for (int i = tid; i < BK * BN / 4; i += 256) {
            int r = i >> 4;
            int c4 = (i & 15) * 4;
            float4 v = *(const float4*)&vh[vbase + (size_t)(k0 + r) * D_ + c4];
            Bs[r][c4 + 0] = v.x; Bs[r][c4 + 1] = v.y;
            Bs[r][c4 + 2] = v.z; Bs[r][c4 + 3] = v.w;
        }
        __syncthreads();
#pragma unroll
        for (int kk = 0; kk < BK; kk++) {
            float ra[TM], rb[TN];
#pragma unroll
            for (int i = 0; i < TM; i++) ra[i] = As[kk][tr * TM + i];
#pragma unroll
            for (int j = 0; j < TN; j++) rb[j] = Bs[kk][tc * TN + j];
#pragma unroll
            for (int i = 0; i < TM; i++)
#pragma unroll
                for (int j = 0; j < TN; j++) acc[i][j] += ra[i] * rb[j];
        }
        __syncthreads();
    }

#pragma unroll
    for (int i = 0; i < TM; i++) {
        int q = bm + tr * TM + i;
#pragma unroll
        for (int j = 0; j < TN; j++) {
            int d = tc * TN + j;
            outh[(size_t)(b * S_ + q) * D_ + h * DH_ + d] = acc[i][j];
        }
    }
}

// ---------------------------------------------------------------------------
// Launch
// ---------------------------------------------------------------------------
extern "C" void kernel_launch(void* const* d_in, const int* in_sizes, int n_in,
                              void* d_out, int out_size)
{
    const float* q   = (const float*)d_in[0];
    const float* k   = (const float*)d_in[1];
    const float* v   = (const float*)d_in[2];
    const float* pe  = (const float*)d_in[3];
    const float* Wq  = (const float*)d_in[4];
    const float* bq  = (const float*)d_in[5];
    const float* Wk  = (const float*)d_in[6];
    const float* bk  = (const float*)d_in[7];
    const float* Wv  = (const float*)d_in[8];
    const float* bv  = (const float*)d_in[9];
    const float* Wp  = (const float*)d_in[10];
    const float* ub  = (const float*)d_in[11];
    const float* vb  = (const float*)d_in[12];
    const float* Wo  = (const float*)d_in[13];
    const float* bo  = (const float*)d_in[14];
    float* out = (float*)d_out;

    float *p_qh, *p_kh, *p_vh, *p_ph, *p_scores, *p_attout;
    cudaGetSymbolAddress((void**)&p_qh, g_qh);
    cudaGetSymbolAddress((void**)&p_kh, g_kh);
    cudaGetSymbolAddress((void**)&p_vh, g_vh);
    cudaGetSymbolAddress((void**)&p_ph, g_ph);
    cudaGetSymbolAddress((void**)&p_scores, g_scores);
    cudaGetSymbolAddress((void**)&p_attout, g_attout);

    // 1) projections: qh/kh/vh (+bias), ph (no bias)
    dim3 gproj(D_ / 128, M_ / 128);          // (8, 32)
    gemm_xwt<<<gproj, 256>>>(q,  Wq, bq,      p_qh, M_, D_, D_);
    gemm_xwt<<<gproj, 256>>>(k,  Wk, bk,      p_kh, M_, D_, D_);
    gemm_xwt<<<gproj, 256>>>(v,  Wv, bv,      p_vh, M_, D_, D_);
    gemm_xwt<<<gproj, 256>>>(pe, Wp, nullptr, p_ph, M_, D_, D_);

    // 2) content scores, then pos scores scatter-accumulated with rel-shift
    dim3 gscore(S_ / 128, S_ / 128, B_ * H_); // (16, 16, 32)
    gemm_scores<<<gscore, 256>>>(p_qh, p_kh, ub, p_scores, 0);
    gemm_scores<<<gscore, 256>>>(p_qh, p_ph, vb, p_scores, 1);

    // 3) scale + softmax in place
    softmax_rows<<<B_ * H_ * S_, 256>>>(p_scores);

    // 4) attn @ V
    dim3 gav(1, S_ / 128, B_ * H_);          // (1, 16, 32)
    gemm_av<<<gav, 256>>>(p_scores, p_vh, p_attout);

    // 5) output projection -> d_out
    gemm_xwt<<<gproj, 256>>>(p_attout, Wo, bo, out, M_, D_, D_);
}

// round 5
// speedup vs baseline: 1.1387x; 1.1387x over previous
#include <cuda_runtime.h>
#include <cuda_bf16.h>
#include <cstdint>
#include <cstddef>

#define B_  2
#define S_  2048
#define D_  1024
#define H_  16
#define DH_ 64
#define M_  (B_ * S_)
#define SP1 (S_ + 1)

typedef __nv_bfloat16 bf16;

static constexpr size_t NMD = (size_t)M_ * D_;
static constexpr size_t NDD = (size_t)D_ * D_;
static constexpr size_t NSS = (size_t)B_ * H_ * S_ * S_;

__device__ __align__(4096) bf16 g_Ah[4 * NMD];
__device__ __align__(4096) bf16 g_Al[4 * NMD];
__device__ __align__(4096) bf16 g_Wh[5 * NDD];
__device__ __align__(4096) bf16 g_Wl[5 * NDD];
__device__ __align__(4096) bf16 g_qhu_h[NMD], g_qhu_l[NMD];
__device__ __align__(4096) bf16 g_qhv_h[NMD], g_qhv_l[NMD];
__device__ __align__(4096) bf16 g_kh_h[NMD],  g_kh_l[NMD];
__device__ __align__(4096) bf16 g_ph_h[NMD],  g_ph_l[NMD];
__device__ __align__(4096) bf16 g_vT_h[NMD],  g_vT_l[NMD];
__device__ __align__(4096) float g_scores[NSS];
__device__ __align__(4096) bf16 g_p_h[NSS], g_p_l[NSS];
__device__ __align__(4096) bf16 g_ao_h[NMD], g_ao_l[NMD];

__device__ __forceinline__ uint32_t smem_u32(const void* p) {
    uint32_t a;
    asm("{ .reg .u64 t; cvta.to.shared.u64 t, %1; cvt.u32.u64 %0, t; }" : "=r"(a) : "l"(p));
    return a;
}
__device__ __forceinline__ void ldsm4(uint32_t* r, uint32_t addr) {
    asm volatile("ldmatrix.sync.aligned.m8n8.x4.shared.b16 {%0,%1,%2,%3}, [%4];"
                 : "=r"(r[0]), "=r"(r[1]), "=r"(r[2]), "=r"(r[3]) : "r"(addr));
}
__device__ __forceinline__ void mma16816(float* c, const uint32_t* a, const uint32_t* b) {
    asm volatile(
        "mma.sync.aligned.m16n8k16.row.col.f32.bf16.bf16.f32 "
        "{%0,%1,%2,%3}, {%4,%5,%6,%7}, {%8,%9}, {%0,%1,%2,%3};"
        : "+f"(c[0]), "+f"(c[1]), "+f"(c[2]), "+f"(c[3])
        : "r"(a[0]), "r"(a[1]), "r"(a[2]), "r"(a[3]), "r"(b[0]), "r"(b[1]));
}

#define EPI_QUV   0
#define EPI_HILO  1
#define EPI_VT    2
#define EPI_SCORE 3
#define EPI_SHIFT 4
#define EPI_AV    5
#define EPI_OUT   6

// C[m,n] = sum_k A[m,k]*B[n,k]; A,B as hi+lo bf16; bf16x3 via warp mma.sync.
// Block: 128 x BN, 8 warps (2 M x 4 N), warp tile 64 x BN/4, BK=32.
template<int BN, int EPI>
__global__ __launch_bounds__(256) void wmma_gemm(
    const bf16* __restrict__ Ah, const bf16* __restrict__ Al,
    const bf16* __restrict__ Bh, const bf16* __restrict__ Bl,
    int Kdim, int lda, int ldb,
    float* __restrict__ outF,
    bf16* __restrict__ o1h, bf16* __restrict__ o1l,
    bf16* __restrict__ o2h, bf16* __restrict__ o2l,
    const float* __restrict__ b1, const float* __restrict__ b2,
    const float* __restrict__ b3)
{
    constexpr int STR = 40;          // smem row stride (bf16)
    constexpr int WN  = BN / 4;      // warp N extent
    constexpr int NI  = WN / 8;      // n8 tiles per warp
    constexpr int NB  = BN / 64;     // B uint4 loads / thread / tile

    __shared__ bf16 sAh[128 * STR], sAl[128 * STR];
    __shared__ bf16 sBh[BN * STR],  sBl[BN * STR];

    const int tid = threadIdx.x, wid = tid >> 5, lane = tid & 31;
    const int wm = wid & 1, wn = wid >> 1;
    const int z = blockIdx.z;
    const int bm = blockIdx.y * 128, bn = blockIdx.x * BN;

    size_t aoff = 0, boff = 0;
    if (EPI == EPI_SCORE || EPI == EPI_SHIFT) {
        aoff = (size_t)(z >> 4) * ((size_t)S_ * D_) + (size_t)(z & 15) * DH_;
        boff = aoff;
    } else if (EPI == EPI_AV) {
        aoff = (size_t)z * S_ * S_;
        boff = (size_t)z * DH_ * S_;
    }

    float acc[4][NI][4];
#pragma unroll
    for (int i = 0; i < 4; i++)
#pragma unroll
        for (int j = 0; j < NI; j++)
#pragma unroll
            for (int c = 0; c < 4; c++) acc[i][j][c] = 0.f;

    const uint32_t uAh = smem_u32(sAh), uAl = smem_u32(sAl);
    const uint32_t uBh = smem_u32(sBh), uBl = smem_u32(sBl);
    const int nch = Kdim / 32;

    uint4 pAh[2], pAl[2], pBh[NB], pBl[NB];

#define GLOAD(k0) do { \
    _Pragma("unroll") \
    for (int j = 0; j < 2; j++) { \
        int u = tid + j * 256, r = u >> 2, c = (u & 3) * 8; \
        const bf16* a0 = Ah + aoff + (size_t)(bm + r) * lda + (k0) + c; \
        const bf16* a1 = Al + aoff + (size_t)(bm + r) * lda + (k0) + c; \
        pAh[j] = *(const uint4*)a0; pAl[j] = *(const uint4*)a1; \
    } \
    _Pragma("unroll") \
    for (int j = 0; j < NB; j++) { \
        int u = tid + j * 256, r = u >> 2, c = (u & 3) * 8; \
        const bf16* b0p = Bh + boff + (size_t)(bn + r) * ldb + (k0) + c; \
        const bf16* b1p = Bl + boff + (size_t)(bn + r) * ldb + (k0) + c; \
        pBh[j] = *(const uint4*)b0p; pBl[j] = *(const uint4*)b1p; \
    } } while (0)

#define SSTORE() do { \
    _Pragma("unroll") \
    for (int j = 0; j < 2; j++) { \
        int u = tid + j * 256, r = u >> 2, c = (u & 3) * 8; \
        *(uint4*)&sAh[r * STR + c] = pAh[j]; \
        *(uint4*)&sAl[r * STR + c] = pAl[j]; \
    } \
    _Pragma("unroll") \
    for (int j = 0; j < NB; j++) { \
        int u = tid + j * 256, r = u >> 2, c = (u & 3) * 8; \
        *(uint4*)&sBh[r * STR + c] = pBh[j]; \
        *(uint4*)&sBl[r * STR + c] = pBl[j]; \
    } } while (0)

    GLOAD(0);
    SSTORE();
    __syncthreads();

    for (int i = 0; i < nch; i++) {
        if (i + 1 < nch) GLOAD((i + 1) * 32);

#pragma unroll
        for (int ks = 0; ks < 32; ks += 16) {
            // B fragments: x4 ldmatrix covers ni pair (2p, 2p+1)
            uint32_t bhf[NI][2], blf[NI][2];
#pragma unroll
            for (int p = 0; p < NI / 2; p++) {
                int g = lane >> 3;
                int row = wn * WN + p * 16 + (lane & 7) + ((g >> 1) << 3);
                int colb = ks * 2 + (g & 1) * 16;
                uint32_t off = (uint32_t)(row * (STR * 2) + colb);
                uint32_t r4[4];
                ldsm4(r4, uBh + off);
                bhf[2 * p][0] = r4[0]; bhf[2 * p][1] = r4[1];
                bhf[2 * p + 1][0] = r4[2]; bhf[2 * p + 1][1] = r4[3];
                ldsm4(r4, uBl + off);
                blf[2 * p][0] = r4[0]; blf[2 * p][1] = r4[1];
                blf[2 * p + 1][0] = r4[2]; blf[2 * p + 1][1] = r4[3];
            }
#pragma unroll
            for (int mi = 0; mi < 4; mi++) {
                int arow = wm * 64 + mi * 16 + (lane & 15);
                int acolb = ks * 2 + (lane >> 4) * 16;
                uint32_t aoffb = (uint32_t)(arow * (STR * 2) + acolb);
                uint32_t ah4[4], al4[4];
                ldsm4(ah4, uAh + aoffb);
                ldsm4(al4, uAl + aoffb);
#pragma unroll
                for (int ni = 0; ni < NI; ni++) {
                    mma16816(acc[mi][ni], ah4, bhf[ni]);
                    mma16816(acc[mi][ni], ah4, blf[ni]);
                    mma16816(acc[mi][ni], al4, bhf[ni]);
                }
            }
        }
        __syncthreads();
        if (i + 1 < nch) {
            SSTORE();
            __syncthreads();
        }
    }

    // ---- epilogue ----
#pragma unroll
    for (int mi = 0; mi < 4; mi++) {
#pragma unroll
        for (int ni = 0; ni < NI; ni++) {
#pragma unroll
            for (int c = 0; c < 4; c++) {
                int m = bm + wm * 64 + mi * 16 + (lane >> 2) + ((c >> 1) << 3);
                int n = bn + wn * WN + ni * 8 + ((lane & 3) << 1) + (c & 1);
                float v = acc[mi][ni][c];

                if constexpr (EPI == EPI_QUV) {
                    float vv = v + b1[n];
                    float x1 = vv + b2[n], x2 = vv + b3[n];
                    size_t o = (size_t)m * D_ + n;
                    bf16 h1 = __float2bfloat16(x1);
                    o1h[o] = h1; o1l[o] = __float2bfloat16(x1 - __bfloat162float(h1));
                    bf16 h2 = __float2bfloat16(x2);
                    o2h[o] = h2; o2l[o] = __float2bfloat16(x2 - __bfloat162float(h2));
                } else if constexpr (EPI == EPI_HILO) {
                    float vv = v + (b1 ? b1[n] : 0.f);
                    size_t o = (size_t)m * D_ + n;
                    bf16 h = __float2bfloat16(vv);
                    o1h[o] = h; o1l[o] = __float2bfloat16(vv - __bfloat162float(h));
                } else if constexpr (EPI == EPI_VT) {
                    float vv = v + b1[n];
                    int b = m >> 11, s = m & (S_ - 1);
                    int h = n >> 6, d = n & 63;
                    size_t o = ((size_t)((b * H_ + h) * DH_ + d)) * S_ + s;
                    bf16 hh = __float2bfloat16(vv);
                    o1h[o] = hh; o1l[o] = __float2bfloat16(vv - __bfloat162float(hh));
                } else if constexpr (EPI == EPI_SCORE) {
                    outF[(size_t)z * S_ * S_ + (size_t)m * S_ + n] = v;
                } else if constexpr (EPI == EPI_SHIFT) {
                    int flat = m * SP1 + n + 1;
                    int qo = (flat >> 11) - 1;
                    int ko = flat & (S_ - 1);
                    if (qo >= 0) {
                        size_t o = (size_t)z * S_ * S_ + (size_t)qo * S_ + ko;
                        outF[o] += v;
                    }
                } else if constexpr (EPI == EPI_AV) {
                    int b = z >> 4, h = z & 15;
                    size_t o = ((size_t)(b * S_ + m)) * D_ + h * DH_ + n;
                    bf16 hh = __float2bfloat16(v);
                    o1h[o] = hh; o1l[o] = __float2bfloat16(v - __bfloat162float(hh));
                } else {  // EPI_OUT
                    outF[(size_t)m * D_ + n] = v + b1[n];
                }
            }
        }
    }
#undef GLOAD
#undef SSTORE
}

__global__ __launch_bounds__(256) void conv_hilo(
    const float* __restrict__ in, bf16* __restrict__ hi, bf16* __restrict__ lo, int n4)
{
    int i = blockIdx.x * 256 + threadIdx.x;
    if (i >= n4) return;
    float4 v = ((const float4*)in)[i];
    bf16 h0 = __float2bfloat16(v.x), h1 = __float2bfloat16(v.y);
    bf16 h2 = __float2bfloat16(v.z), h3 = __float2bfloat16(v.w);
    hi[i * 4 + 0] = h0; hi[i * 4 + 1] = h1; hi[i * 4 + 2] = h2; hi[i * 4 + 3] = h3;
    lo[i * 4 + 0] = __float2bfloat16(v.x - __bfloat162float(h0));
    lo[i * 4 + 1] = __float2bfloat16(v.y - __bfloat162float(h1));
    lo[i * 4 + 2] = __float2bfloat16(v.z - __bfloat162float(h2));
    lo[i * 4 + 3] = __float2bfloat16(v.w - __bfloat162float(h3));
}

__global__ __launch_bounds__(256) void softmax_rows(
    const float* __restrict__ scores, bf16* __restrict__ ph, bf16* __restrict__ pl)
{
    const size_t rb = (size_t)blockIdx.x * S_;
    const int t0 = threadIdx.x;
    float vals[8];
    float mx = -3.4e38f;
#pragma unroll
    for (int t = 0; t < 8; t++) {
        float s = scores[rb + t0 + t * 256] * 0.03125f;   // 1/sqrt(1024)
        vals[t] = s; mx = fmaxf(mx, s);
    }
    __shared__ float smax[8], ssum[8];
#pragma unroll
    for (int o = 16; o > 0; o >>= 1) mx = fmaxf(mx, __shfl_xor_sync(0xffffffffu, mx, o));
    if ((t0 & 31) == 0) smax[t0 >> 5] = mx;
    __syncthreads();
    float rmax = smax[0];
#pragma unroll
    for (int w = 1; w < 8; w++) rmax = fmaxf(rmax, smax[w]);
    float sum = 0.f;
#pragma unroll
    for (int t = 0; t < 8; t++) { vals[t] = __expf(vals[t] - rmax); sum += vals[t]; }
#pragma unroll
    for (int o = 16; o > 0; o >>= 1) sum += __shfl_xor_sync(0xffffffffu, sum, o);
    if ((t0 & 31) == 0) ssum[t0 >> 5] = sum;
    __syncthreads();
    float tot = 0.f;
#pragma unroll
    for (int w = 0; w < 8; w++) tot += ssum[w];
    const float inv = 1.f / tot;
#pragma unroll
    for (int t = 0; t < 8; t++) {
        float p = vals[t] * inv;
        bf16 h = __float2bfloat16(p);
        ph[rb + t0 + t * 256] = h;
        pl[rb + t0 + t * 256] = __float2bfloat16(p - __bfloat162float(h));
    }
}

extern "C" void kernel_launch(void* const* d_in, const int* in_sizes, int n_in,
                              void* d_out, int out_size)
{
    const float* q   = (const float*)d_in[0];
    const float* k   = (const float*)d_in[1];
    const float* v   = (const float*)d_in[2];
    const float* pe  = (const float*)d_in[3];
    const float* Wq  = (const float*)d_in[4];
    const float* bq  = (const float*)d_in[5];
    const float* Wk  = (const float*)d_in[6];
    const float* bk  = (const float*)d_in[7];
    const float* Wv  = (const float*)d_in[8];
    const float* bv  = (const float*)d_in[9];
    const float* Wp  = (const float*)d_in[10];
    const float* ub  = (const float*)d_in[11];
    const float* vb  = (const float*)d_in[12];
    const float* Wo  = (const float*)d_in[13];
    const float* bo  = (const float*)d_in[14];
    float* out = (float*)d_out;

    bf16 *Ah, *Al, *Wh, *Wl, *qhu_h, *qhu_l, *qhv_h, *qhv_l, *kh_h, *kh_l;
    bf16 *ph_h, *ph_l, *vT_h, *vT_l, *p_h, *p_l, *ao_h, *ao_l;
    float *scores;
    cudaGetSymbolAddress((void**)&Ah, g_Ah);
    cudaGetSymbolAddress((void**)&Al, g_Al);
    cudaGetSymbolAddress((void**)&Wh, g_Wh);
    cudaGetSymbolAddress((void**)&Wl, g_Wl);
    cudaGetSymbolAddress((void**)&qhu_h, g_qhu_h);
    cudaGetSymbolAddress((void**)&qhu_l, g_qhu_l);
    cudaGetSymbolAddress((void**)&qhv_h, g_qhv_h);
    cudaGetSymbolAddress((void**)&qhv_l, g_qhv_l);
    cudaGetSymbolAddress((void**)&kh_h, g_kh_h);
    cudaGetSymbolAddress((void**)&kh_l, g_kh_l);
    cudaGetSymbolAddress((void**)&ph_h, g_ph_h);
    cudaGetSymbolAddress((void**)&ph_l, g_ph_l);
    cudaGetSymbolAddress((void**)&vT_h, g_vT_h);
    cudaGetSymbolAddress((void**)&vT_l, g_vT_l);
    cudaGetSymbolAddress((void**)&scores, g_scores);
    cudaGetSymbolAddress((void**)&p_h, g_p_h);
    cudaGetSymbolAddress((void**)&p_l, g_p_l);
    cudaGetSymbolAddress((void**)&ao_h, g_ao_h);
    cudaGetSymbolAddress((void**)&ao_l, g_ao_l);

    const int nMD4 = (int)(NMD / 4), nDD4 = (int)(NDD / 4);
    conv_hilo<<<nMD4 / 256, 256>>>(q,  Ah + 0 * NMD, Al + 0 * NMD, nMD4);
    conv_hilo<<<nMD4 / 256, 256>>>(k,  Ah + 1 * NMD, Al + 1 * NMD, nMD4);
    conv_hilo<<<nMD4 / 256, 256>>>(v,  Ah + 2 * NMD, Al + 2 * NMD, nMD4);
    conv_hilo<<<nMD4 / 256, 256>>>(pe, Ah + 3 * NMD, Al + 3 * NMD, nMD4);
    conv_hilo<<<nDD4 / 256, 256>>>(Wq, Wh + 0 * NDD, Wl + 0 * NDD, nDD4);
    conv_hilo<<<nDD4 / 256, 256>>>(Wk, Wh + 1 * NDD, Wl + 1 * NDD, nDD4);
    conv_hilo<<<nDD4 / 256, 256>>>(Wv, Wh + 2 * NDD, Wl + 2 * NDD, nDD4);
    conv_hilo<<<nDD4 / 256, 256>>>(Wp, Wh + 3 * NDD, Wl + 3 * NDD, nDD4);
    conv_hilo<<<nDD4 / 256, 256>>>(Wo, Wh + 4 * NDD, Wl + 4 * NDD, nDD4);

    // 1) projections
    dim3 gp(D_ / 128, M_ / 128, 1);
    wmma_gemm<128, EPI_QUV><<<gp, 256>>>(
        Ah, Al, Wh, Wl, D_, D_, D_,
        nullptr, qhu_h, qhu_l, qhv_h, qhv_l, bq, ub, vb);
    wmma_gemm<128, EPI_HILO><<<gp, 256>>>(
        Ah + NMD, Al + NMD, Wh + NDD, Wl + NDD, D_, D_, D_,
        nullptr, kh_h, kh_l, nullptr, nullptr, bk, nullptr, nullptr);
    wmma_gemm<128, EPI_VT><<<gp, 256>>>(
        Ah + 2 * NMD, Al + 2 * NMD, Wh + 2 * NDD, Wl + 2 * NDD, D_, D_, D_,
        nullptr, vT_h, vT_l, nullptr, nullptr, bv, nullptr, nullptr);
    wmma_gemm<128, EPI_HILO><<<gp, 256>>>(
        Ah + 3 * NMD, Al + 3 * NMD, Wh + 3 * NDD, Wl + 3 * NDD, D_, D_, D_,
        nullptr, ph_h, ph_l, nullptr, nullptr, nullptr, nullptr, nullptr);

    // 2) content scores; pos scores with fused rel-shift scatter-add
    dim3 gs(S_ / 128, S_ / 128, B_ * H_);
    wmma_gemm<128, EPI_SCORE><<<gs, 256>>>(
        qhu_h, qhu_l, kh_h, kh_l, DH_, D_, D_,
        scores, nullptr, nullptr, nullptr, nullptr, nullptr, nullptr, nullptr);
    wmma_gemm<128, EPI_SHIFT><<<gs, 256>>>(
        qhv_h, qhv_l, ph_h, ph_l, DH_, D_, D_,
        scores, nullptr, nullptr, nullptr, nullptr, nullptr, nullptr, nullptr);

    // 3) scale + softmax -> bf16 hi/lo probs
    softmax_rows<<<B_ * H_ * S_, 256>>>(scores, p_h, p_l);

    // 4) attn @ V
    dim3 ga(1, S_ / 128, B_ * H_);
    wmma_gemm<64, EPI_AV><<<ga, 256>>>(
        p_h, p_l, vT_h, vT_l, S_, S_, S_,
        nullptr, ao_h, ao_l, nullptr, nullptr, nullptr, nullptr, nullptr);

    // 5) output projection
    wmma_gemm<128, EPI_OUT><<<gp, 256>>>(
        ao_h, ao_l, Wh + 4 * NDD, Wl + 4 * NDD, D_, D_, D_,
        out, nullptr, nullptr, nullptr, nullptr, bo, nullptr, nullptr);
}

// round 7
// speedup vs baseline: 1.6123x; 1.4158x over previous
#include <cuda_runtime.h>
#include <cuda_bf16.h>
#include <cstdint>
#include <cstddef>

#define B_  2
#define S_  2048
#define D_  1024
#define H_  16
#define DH_ 64
#define M_  (B_ * S_)
#define SP1 (S_ + 1)

typedef __nv_bfloat16 bf16;

static constexpr size_t NMD = (size_t)M_ * D_;
static constexpr size_t NDD = (size_t)D_ * D_;
static constexpr size_t NSS = (size_t)B_ * H_ * S_ * S_;

__device__ __align__(4096) bf16 g_Ah[4 * NMD];
__device__ __align__(4096) bf16 g_Al[4 * NMD];
__device__ __align__(4096) bf16 g_Wh[5 * NDD];
__device__ __align__(4096) bf16 g_Wl[5 * NDD];
__device__ __align__(4096) bf16 g_qhu_h[NMD], g_qhu_l[NMD];
__device__ __align__(4096) bf16 g_qhv_h[NMD], g_qhv_l[NMD];
__device__ __align__(4096) bf16 g_kh_h[NMD],  g_kh_l[NMD];
__device__ __align__(4096) bf16 g_ph_h[NMD],  g_ph_l[NMD];
__device__ __align__(4096) bf16 g_vT_h[NMD],  g_vT_l[NMD];
__device__ __align__(4096) float g_scores[NSS];
__device__ __align__(4096) bf16 g_p_h[NSS], g_p_l[NSS];
__device__ __align__(4096) bf16 g_ao_h[NMD], g_ao_l[NMD];

__device__ __forceinline__ uint32_t smem_u32(const void* p) {
    uint32_t a;
    asm("{ .reg .u64 t; cvta.to.shared.u64 t, %1; cvt.u32.u64 %0, t; }" : "=r"(a) : "l"(p));
    return a;
}
__device__ __forceinline__ void ldsm4(uint32_t* r, uint32_t addr) {
    asm volatile("ldmatrix.sync.aligned.m8n8.x4.shared.b16 {%0,%1,%2,%3}, [%4];"
                 : "=r"(r[0]), "=r"(r[1]), "=r"(r[2]), "=r"(r[3]) : "r"(addr));
}
__device__ __forceinline__ void mma16816(float* c, const uint32_t* a, const uint32_t* b) {
    asm volatile(
        "mma.sync.aligned.m16n8k16.row.col.f32.bf16.bf16.f32 "
        "{%0,%1,%2,%3}, {%4,%5,%6,%7}, {%8,%9}, {%0,%1,%2,%3};"
        : "+f"(c[0]), "+f"(c[1]), "+f"(c[2]), "+f"(c[3])
        : "r"(a[0]), "r"(a[1]), "r"(a[2]), "r"(a[3]), "r"(b[0]), "r"(b[1]));
}
#define CP16(dst, src) \
    asm volatile("cp.async.ca.shared.global [%0], [%1], 16;" :: "r"(dst), "l"(src))
#define CPCOMMIT() asm volatile("cp.async.commit_group;" ::: "memory")
#define CPWAIT1()  asm volatile("cp.async.wait_group 1;" ::: "memory")
#define CPWAIT0()  asm volatile("cp.async.wait_group 0;" ::: "memory")

#define EPI_QUV   0
#define EPI_HILO  1
#define EPI_VT    2
#define EPI_SCORE 3
#define EPI_SHIFT 4
#define EPI_AV    5
#define EPI_OUT   6

// C[m,n] = sum_k A[m,k]*B[n,k]; A,B hi+lo bf16; NP passes (1:AhBh 2:+AhBl 3:+AlBh).
// Block 128 x BN, 8 warps (2M x 4N), BK=32, 2-stage cp.async pipeline.
template<int BN, int EPI, int NP>
__global__ __launch_bounds__(256) void wmma_gemm(
    const bf16* __restrict__ Ah, const bf16* __restrict__ Al,
    const bf16* __restrict__ Bh, const bf16* __restrict__ Bl,
    int Kdim, int lda, int ldb,
    float* __restrict__ outF,
    bf16* __restrict__ o1h, bf16* __restrict__ o1l,
    bf16* __restrict__ o2h, bf16* __restrict__ o2l,
    const float* __restrict__ b1, const float* __restrict__ b2,
    const float* __restrict__ b3)
{
    constexpr int STR = 40;                 // smem row stride (bf16), 80 B
    constexpr int WN  = BN / 4;
    constexpr int NI  = WN / 8;
    constexpr int NB  = BN / 64;            // B 16B-loads per thread per array
    constexpr int SA  = 128 * STR * 2;      // 10240 B
    constexpr int SAL = (NP >= 3) ? SA : 0;
    constexpr int SB  = BN * STR * 2;
    constexpr int SS  = SA + SAL + 2 * SB;  // per-stage bytes

    extern __shared__ char sm[];

    const int tid = threadIdx.x, wid = tid >> 5, lane = tid & 31;
    const int wm = wid & 1, wn = wid >> 1;
    const int z = blockIdx.z;
    const int bm = blockIdx.y * 128, bn = blockIdx.x * BN;

    size_t aoff = 0, boff = 0;
    if (EPI == EPI_SCORE || EPI == EPI_SHIFT) {
        aoff = (size_t)(z >> 4) * ((size_t)S_ * D_) + (size_t)(z & 15) * DH_;
        boff = aoff;
    } else if (EPI == EPI_AV) {
        aoff = (size_t)z * S_ * S_;
        boff = (size_t)z * DH_ * S_;
    }

    float acc[4][NI][4];
#pragma unroll
    for (int i = 0; i < 4; i++)
#pragma unroll
        for (int j = 0; j < NI; j++)
#pragma unroll
            for (int c = 0; c < 4; c++) acc[i][j][c] = 0.f;

    const int nch = Kdim / 32;

    auto issue = [&](int i, int st) {
        const int k0 = i * 32;
        char* base = sm + st * SS;
        const uint32_t uA  = smem_u32(base);
        const uint32_t uAl2 = uA + SA;
        const uint32_t uB  = uA + SA + SAL;
        const uint32_t uBl2 = uB + SB;
#pragma unroll
        for (int j = 0; j < 2; j++) {
            int idx = tid + j * 256;
            int r = idx >> 2, c4 = idx & 3;
            uint32_t doff = (uint32_t)(r * (STR * 2) + c4 * 16);
            const bf16* s0 = Ah + aoff + (size_t)(bm + r) * lda + k0 + c4 * 8;
            CP16(uA + doff, s0);
            if (NP >= 3) {
                const bf16* s1 = Al + aoff + (size_t)(bm + r) * lda + k0 + c4 * 8;
                CP16(uAl2 + doff, s1);
            }
        }
#pragma unroll
        for (int j = 0; j < NB; j++) {
            int idx = tid + j * 256;
            int r = idx >> 2, c4 = idx & 3;
            uint32_t doff = (uint32_t)(r * (STR * 2) + c4 * 16);
            const bf16* s0 = Bh + boff + (size_t)(bn + r) * ldb + k0 + c4 * 8;
            const bf16* s1 = Bl + boff + (size_t)(bn + r) * ldb + k0 + c4 * 8;
            CP16(uB + doff, s0);
            CP16(uBl2 + doff, s1);
        }
        CPCOMMIT();
    };

    issue(0, 0);

    for (int i = 0; i < nch; i++) {
        if (i + 1 < nch) { issue(i + 1, (i + 1) & 1); CPWAIT1(); }
        else             { CPWAIT0(); }
        __syncthreads();

        char* base = sm + (i & 1) * SS;
        const uint32_t uAh = smem_u32(base);
        const uint32_t uAl = uAh + SA;
        const uint32_t uBh = uAh + SA + SAL;
        const uint32_t uBl = uBh + SB;

#pragma unroll
        for (int ks = 0; ks < 32; ks += 16) {
            uint32_t bhf[NI][2], blf[NI][2];
#pragma unroll
            for (int p = 0; p < NI / 2; p++) {
                int g = lane >> 3;
                int row = wn * WN + p * 16 + (lane & 7) + ((g >> 1) << 3);
                int colb = ks * 2 + (g & 1) * 16;
                uint32_t off = (uint32_t)(row * (STR * 2) + colb);
                uint32_t r4[4];
                ldsm4(r4, uBh + off);
                bhf[2 * p][0] = r4[0]; bhf[2 * p][1] = r4[1];
                bhf[2 * p + 1][0] = r4[2]; bhf[2 * p + 1][1] = r4[3];
                ldsm4(r4, uBl + off);
                blf[2 * p][0] = r4[0]; blf[2 * p][1] = r4[1];
                blf[2 * p + 1][0] = r4[2]; blf[2 * p + 1][1] = r4[3];
            }
#pragma unroll
            for (int mi = 0; mi < 4; mi++) {
                int arow = wm * 64 + mi * 16 + (lane & 15);
                int acolb = ks * 2 + (lane >> 4) * 16;
                uint32_t aob = (uint32_t)(arow * (STR * 2) + acolb);
                uint32_t ah4[4], al4[4];
                ldsm4(ah4, uAh + aob);
                if (NP >= 3) ldsm4(al4, uAl + aob);
#pragma unroll
                for (int ni = 0; ni < NI; ni++) {
                    mma16816(acc[mi][ni], ah4, bhf[ni]);
                    if (NP >= 2) mma16816(acc[mi][ni], ah4, blf[ni]);
                    if (NP >= 3) mma16816(acc[mi][ni], al4, bhf[ni]);
                }
            }
        }
        __syncthreads();
    }

    // ---- epilogue ----
#pragma unroll
    for (int mi = 0; mi < 4; mi++) {
#pragma unroll
        for (int ni = 0; ni < NI; ni++) {
#pragma unroll
            for (int c = 0; c < 4; c++) {
                int m = bm + wm * 64 + mi * 16 + (lane >> 2) + ((c >> 1) << 3);
                int n = bn + wn * WN + ni * 8 + ((lane & 3) << 1) + (c & 1);
                float v = acc[mi][ni][c];

                if constexpr (EPI == EPI_QUV) {
                    float vv = v + b1[n];
                    float x1 = vv + b2[n], x2 = vv + b3[n];
                    size_t o = (size_t)m * D_ + n;
                    bf16 h1 = __float2bfloat16(x1);
                    o1h[o] = h1; o1l[o] = __float2bfloat16(x1 - __bfloat162float(h1));
                    bf16 h2 = __float2bfloat16(x2);
                    o2h[o] = h2; o2l[o] = __float2bfloat16(x2 - __bfloat162float(h2));
                } else if constexpr (EPI == EPI_HILO) {
                    float vv = v + (b1 ? b1[n] : 0.f);
                    size_t o = (size_t)m * D_ + n;
                    bf16 h = __float2bfloat16(vv);
                    o1h[o] = h; o1l[o] = __float2bfloat16(vv - __bfloat162float(h));
                } else if constexpr (EPI == EPI_VT) {
                    float vv = v + b1[n];
                    int b = m >> 11, s = m & (S_ - 1);
                    int h = n >> 6, d = n & 63;
                    size_t o = ((size_t)((b * H_ + h) * DH_ + d)) * S_ + s;
                    bf16 hh = __float2bfloat16(vv);
                    o1h[o] = hh; o1l[o] = __float2bfloat16(vv - __bfloat162float(hh));
                } else if constexpr (EPI == EPI_SCORE) {
                    outF[(size_t)z * S_ * S_ + (size_t)m * S_ + n] = v;
                } else if constexpr (EPI == EPI_SHIFT) {
                    int flat = m * SP1 + n + 1;
                    int qo = (flat >> 11) - 1;
                    int ko = flat & (S_ - 1);
                    if (qo >= 0) {
                        size_t o = (size_t)z * S_ * S_ + (size_t)qo * S_ + ko;
                        outF[o] += v;
                    }
                } else if constexpr (EPI == EPI_AV) {
                    int b = z >> 4, h = z & 15;
                    size_t o = ((size_t)(b * S_ + m)) * D_ + h * DH_ + n;
                    bf16 hh = __float2bfloat16(v);
                    o1h[o] = hh; o1l[o] = __float2bfloat16(v - __bfloat162float(hh));
                } else {  // EPI_OUT
                    outF[(size_t)m * D_ + n] = v + b1[n];
                }
            }
        }
    }
}

struct Ptr5 { const float* p[5]; };

__global__ __launch_bounds__(256) void conv_multi(
    Ptr5 in, bf16* __restrict__ hi, bf16* __restrict__ lo, size_t perN, int n4)
{
    int i = blockIdx.x * 256 + threadIdx.x;
    if (i >= n4) return;
    int w = blockIdx.y;
    const float* src = in.p[w];
    bf16* h = hi + (size_t)w * perN;
    bf16* l = lo + (size_t)w * perN;
    float4 v = ((const float4*)src)[i];
    bf16 h0 = __float2bfloat16(v.x), h1 = __float2bfloat16(v.y);
    bf16 h2 = __float2bfloat16(v.z), h3 = __float2bfloat16(v.w);
    h[i * 4 + 0] = h0; h[i * 4 + 1] = h1; h[i * 4 + 2] = h2; h[i * 4 + 3] = h3;
    l[i * 4 + 0] = __float2bfloat16(v.x - __bfloat162float(h0));
    l[i * 4 + 1] = __float2bfloat16(v.y - __bfloat162float(h1));
    l[i * 4 + 2] = __float2bfloat16(v.z - __bfloat162float(h2));
    l[i * 4 + 3] = __float2bfloat16(v.w - __bfloat162float(h3));
}

__global__ __launch_bounds__(256) void softmax_rows(
    const float* __restrict__ scores, bf16* __restrict__ ph, bf16* __restrict__ pl)
{
    const size_t rb = (size_t)blockIdx.x * S_;
    const int t0 = threadIdx.x;
    float vals[8];
    float mx = -3.4e38f;
#pragma unroll
    for (int t = 0; t < 8; t++) {
        float s = scores[rb + t0 + t * 256] * 0.03125f;
        vals[t] = s; mx = fmaxf(mx, s);
    }
    __shared__ float smax[8], ssum[8];
#pragma unroll
    for (int o = 16; o > 0; o >>= 1) mx = fmaxf(mx, __shfl_xor_sync(0xffffffffu, mx, o));
    if ((t0 & 31) == 0) smax[t0 >> 5] = mx;
    __syncthreads();
    float rmax = smax[0];
#pragma unroll
    for (int w = 1; w < 8; w++) rmax = fmaxf(rmax, smax[w]);
    float sum = 0.f;
#pragma unroll
    for (int t = 0; t < 8; t++) { vals[t] = __expf(vals[t] - rmax); sum += vals[t]; }
#pragma unroll
    for (int o = 16; o > 0; o >>= 1) sum += __shfl_xor_sync(0xffffffffu, sum, o);
    if ((t0 & 31) == 0) ssum[t0 >> 5] = sum;
    __syncthreads();
    float tot = 0.f;
#pragma unroll
    for (int w = 0; w < 8; w++) tot += ssum[w];
    const float inv = 1.f / tot;
#pragma unroll
    for (int t = 0; t < 8; t++) {
        float p = vals[t] * inv;
        bf16 h = __float2bfloat16(p);
        ph[rb + t0 + t * 256] = h;
        pl[rb + t0 + t * 256] = __float2bfloat16(p - __bfloat162float(h));
    }
}

extern "C" void kernel_launch(void* const* d_in, const int* in_sizes, int n_in,
                              void* d_out, int out_size)
{
    const float* q   = (const float*)d_in[0];
    const float* k   = (const float*)d_in[1];
    const float* v   = (const float*)d_in[2];
    const float* pe  = (const float*)d_in[3];
    const float* Wq  = (const float*)d_in[4];
    const float* bq  = (const float*)d_in[5];
    const float* Wk  = (const float*)d_in[6];
    const float* bk  = (const float*)d_in[7];
    const float* Wv  = (const float*)d_in[8];
    const float* bv  = (const float*)d_in[9];
    const float* Wp  = (const float*)d_in[10];
    const float* ub  = (const float*)d_in[11];
    const float* vb  = (const float*)d_in[12];
    const float* Wo  = (const float*)d_in[13];
    const float* bo  = (const float*)d_in[14];
    float* out = (float*)d_out;

    bf16 *Ah, *Al, *Wh, *Wl, *qhu_h, *qhu_l, *qhv_h, *qhv_l, *kh_h, *kh_l;
    bf16 *ph_h, *ph_l, *vT_h, *vT_l, *p_h, *p_l, *ao_h, *ao_l;
    float *scores;
    cudaGetSymbolAddress((void**)&Ah, g_Ah);
    cudaGetSymbolAddress((void**)&Al, g_Al);
    cudaGetSymbolAddress((void**)&Wh, g_Wh);
    cudaGetSymbolAddress((void**)&Wl, g_Wl);
    cudaGetSymbolAddress((void**)&qhu_h, g_qhu_h);
    cudaGetSymbolAddress((void**)&qhu_l, g_qhu_l);
    cudaGetSymbolAddress((void**)&qhv_h, g_qhv_h);
    cudaGetSymbolAddress((void**)&qhv_l, g_qhv_l);
    cudaGetSymbolAddress((void**)&kh_h, g_kh_h);
    cudaGetSymbolAddress((void**)&kh_l, g_kh_l);
    cudaGetSymbolAddress((void**)&ph_h, g_ph_h);
    cudaGetSymbolAddress((void**)&ph_l, g_ph_l);
    cudaGetSymbolAddress((void**)&vT_h, g_vT_h);
    cudaGetSymbolAddress((void**)&vT_l, g_vT_l);
    cudaGetSymbolAddress((void**)&scores, g_scores);
    cudaGetSymbolAddress((void**)&p_h, g_p_h);
    cudaGetSymbolAddress((void**)&p_l, g_p_l);
    cudaGetSymbolAddress((void**)&ao_h, g_ao_h);
    cudaGetSymbolAddress((void**)&ao_l, g_ao_l);

    const int DS_P2_128 = 2 * (10240 + 2 * 10240);           // 61440
    const int DS_P3_128 = 2 * (2 * 10240 + 2 * 10240);       // 81920
    const int DS_P3_64  = 2 * (2 * 10240 + 2 * 5120);        // 61440
    cudaFuncSetAttribute(wmma_gemm<128, EPI_QUV, 2>,   cudaFuncAttributeMaxDynamicSharedMemorySize, DS_P2_128);
    cudaFuncSetAttribute(wmma_gemm<128, EPI_HILO, 2>,  cudaFuncAttributeMaxDynamicSharedMemorySize, DS_P2_128);
    cudaFuncSetAttribute(wmma_gemm<128, EPI_VT, 3>,    cudaFuncAttributeMaxDynamicSharedMemorySize, DS_P3_128);
    cudaFuncSetAttribute(wmma_gemm<128, EPI_SCORE, 2>, cudaFuncAttributeMaxDynamicSharedMemorySize, DS_P2_128);
    cudaFuncSetAttribute(wmma_gemm<128, EPI_SHIFT, 2>, cudaFuncAttributeMaxDynamicSharedMemorySize, DS_P2_128);
    cudaFuncSetAttribute(wmma_gemm<64,  EPI_AV, 3>,    cudaFuncAttributeMaxDynamicSharedMemorySize, DS_P3_64);
    cudaFuncSetAttribute(wmma_gemm<128, EPI_OUT, 3>,   cudaFuncAttributeMaxDynamicSharedMemorySize, DS_P3_128);

    const int nMD4 = (int)(NMD / 4), nDD4 = (int)(NDD / 4);
    Ptr5 pin;  pin.p[0] = q;  pin.p[1] = k;  pin.p[2] = v;  pin.p[3] = pe; pin.p[4] = nullptr;
    Ptr5 pw;   pw.p[0] = Wq; pw.p[1] = Wk; pw.p[2] = Wv; pw.p[3] = Wp; pw.p[4] = Wo;
    conv_multi<<<dim3(nMD4 / 256, 4), 256>>>(pin, Ah, Al, NMD, nMD4);
    conv_multi<<<dim3(nDD4 / 256, 5), 256>>>(pw,  Wh, Wl, NDD, nDD4);

    dim3 gp(D_ / 128, M_ / 128, 1);
    wmma_gemm<128, EPI_QUV, 2><<<gp, 256, DS_P2_128>>>(
        Ah, Al, Wh, Wl, D_, D_, D_,
        nullptr, qhu_h, qhu_l, qhv_h, qhv_l, bq, ub, vb);
    wmma_gemm<128, EPI_HILO, 2><<<gp, 256, DS_P2_128>>>(
        Ah + NMD, Al + NMD, Wh + NDD, Wl + NDD, D_, D_, D_,
        nullptr, kh_h, kh_l, nullptr, nullptr, bk, nullptr, nullptr);
    wmma_gemm<128, EPI_VT, 3><<<gp, 256, DS_P3_128>>>(
        Ah + 2 * NMD, Al + 2 * NMD, Wh + 2 * NDD, Wl + 2 * NDD, D_, D_, D_,
        nullptr, vT_h, vT_l, nullptr, nullptr, bv, nullptr, nullptr);
    wmma_gemm<128, EPI_HILO, 2><<<gp, 256, DS_P2_128>>>(
        Ah + 3 * NMD, Al + 3 * NMD, Wh + 3 * NDD, Wl + 3 * NDD, D_, D_, D_,
        nullptr, ph_h, ph_l, nullptr, nullptr, nullptr, nullptr, nullptr);

    dim3 gs(S_ / 128, S_ / 128, B_ * H_);
    wmma_gemm<128, EPI_SCORE, 2><<<gs, 256, DS_P2_128>>>(
        qhu_h, qhu_l, kh_h, kh_l, DH_, D_, D_,
        scores, nullptr, nullptr, nullptr, nullptr, nullptr, nullptr, nullptr);
    wmma_gemm<128, EPI_SHIFT, 2><<<gs, 256, DS_P2_128>>>(
        qhv_h, qhv_l, ph_h, ph_l, DH_, D_, D_,
        scores, nullptr, nullptr, nullptr, nullptr, nullptr, nullptr, nullptr);

    softmax_rows<<<B_ * H_ * S_, 256>>>(scores, p_h, p_l);

    dim3 ga(1, S_ / 128, B_ * H_);
    wmma_gemm<64, EPI_AV, 3><<<ga, 256, DS_P3_64>>>(
        p_h, p_l, vT_h, vT_l, S_, S_, S_,
        nullptr, ao_h, ao_l, nullptr, nullptr, nullptr, nullptr, nullptr);

    wmma_gemm<128, EPI_OUT, 3><<<gp, 256, DS_P3_128>>>(
        ao_h, ao_l, Wh + 4 * NDD, Wl + 4 * NDD, D_, D_, D_,
        out, nullptr, nullptr, nullptr, nullptr, bo, nullptr, nullptr);
}